// round 12
// baseline (speedup 1.0000x reference)
#include <cuda_runtime.h>

#define NA 102000
#define DIMS 85
#define NCLS 80
#define KSEL 8192
#define KW 128           // 8192/64 words
#define MAXD 300
#define CAND_CAP 16384
#define CONF_T 0.25f
#define IOU_T 0.45f

typedef unsigned long long ull;

// ---------------- scratch (__device__ globals; no allocation) ----------------
__device__ float d_scores[NA];
__device__ float d_classes[NA];
__device__ float4 d_boxes[NA];          // yxyx
__device__ unsigned int d_hist[65536];
__device__ int d_binB;
__device__ int d_ncand;
__device__ ull d_ckey[CAND_CAP];
__device__ int d_cidx[CAND_CAP];
__device__ int d_rank[CAND_CAP];
__device__ float4 d_tbox[KSEL];
__device__ float d_tscore[KSEL];
__device__ float d_tclass[KSEL];
__device__ ull d_mask[(size_t)KSEL * KW];   // 8 MB suppression-bit matrix (upper triangle)
__device__ ull d_diag[KSEL];                // each row's own-chunk word (bits j>i only)

// ---------------- init ----------------
__global__ void k_init() {
    int i = blockIdx.x * blockDim.x + threadIdx.x;
    if (i < 65536) d_hist[i] = 0u;
    if (i < CAND_CAP) d_rank[i] = 0;
    if (i == 0) d_ncand = 0;
}

// ---------------- scoring + histogram ----------------
__global__ void k_score(const float* __restrict__ preds) {
    __shared__ float sp[128 * DIMS];
    int base = blockIdx.x * 128;
    int nanch = NA - base; if (nanch > 128) nanch = 128;
    int total = nanch * DIMS;                     // divisible by 4 (nanch % 4 == 0 incl. tail 112)
    const float4* src4 = (const float4*)(preds + (size_t)base * DIMS);
    float4* sp4 = (float4*)sp;
    int total4 = total >> 2;
    for (int i = threadIdx.x; i < total4; i += 128) sp4[i] = src4[i];
    __syncthreads();

    int a = threadIdx.x;
    unsigned amask = __ballot_sync(0xffffffffu, a < nanch);
    if (a >= nanch) return;

    const float* p = sp + a * DIMS;
    float obj = p[4];
    float best = -1.0f; int bc = 0;
#pragma unroll
    for (int c = 0; c < NCLS; c++) {
        float v = __fmul_rn(p[5 + c], obj);   // per-class product, first-max argmax (matches jnp.argmax)
        if (v > best) { best = v; bc = c; }
    }
    float score = (obj > CONF_T) ? best : 0.0f;
    int gi = base + a;
    d_scores[gi] = score;
    d_classes[gi] = (float)bc;
    float x = p[0], y = p[1], w = p[2], h = p[3];
    float hw = __fmul_rn(w, 0.5f), hh = __fmul_rn(h, 0.5f);   // exact (x0.5)
    d_boxes[gi] = make_float4(__fsub_rn(y, hh), __fsub_rn(x, hw),
                              __fadd_rn(y, hh), __fadd_rn(x, hw));

    int bin = (int)(__float_as_uint(score) >> 16);   // score >= 0 -> monotone bits
    unsigned grp = __match_any_sync(amask, bin);
    int leader = __ffs(grp) - 1;
    if ((int)(threadIdx.x & 31) == leader)
        atomicAdd(&d_hist[bin], (unsigned)__popc(grp));
}

// ---------------- find cutoff bin: smallest-count superset of top-K ----------------
__global__ void k_cutoff() {
    __shared__ unsigned int ssum[1024];
    __shared__ unsigned int ssuf[1024];
    int t = threadIdx.x;
    int b0 = t * 64;
    unsigned s = 0;
    const uint4* h4 = (const uint4*)(d_hist + b0);   // 64 bins = 16 uint4 (16B-aligned)
#pragma unroll
    for (int k = 0; k < 16; k++) {
        uint4 v = h4[k];
        s += v.x + v.y + v.z + v.w;
    }
    ssum[t] = s; ssuf[t] = s;
    __syncthreads();
    for (int off = 1; off < 1024; off <<= 1) {   // inclusive suffix scan
        unsigned add = (t + off < 1024) ? ssuf[t + off] : 0u;
        __syncthreads();
        ssuf[t] += add;
        __syncthreads();
    }
    unsigned excl = (t < 1023) ? ssuf[t + 1] : 0u;
    if (excl < KSEL && excl + ssum[t] >= KSEL) {
        unsigned acc = excl;
        int bin = b0;
        for (int k = 63; k >= 0; k--) {
            acc += d_hist[b0 + k];
            if (acc >= KSEL) { bin = b0 + k; break; }
        }
        d_binB = bin;
    }
}

// ---------------- compact candidates (key16 >= cutoff bin, nonzero) ----------------
__global__ void k_compact() {
    int i = blockIdx.x * blockDim.x + threadIdx.x;
    bool q = false;
    unsigned bits = 0;
    if (i < NA) {
        bits = __float_as_uint(d_scores[i]);
        q = (bits != 0u) && ((int)(bits >> 16) >= d_binB);
    }
    unsigned m = __ballot_sync(0xffffffffu, q);
    if (q) {
        int lane = threadIdx.x & 31;
        int nbefore = __popc(m & ((1u << lane) - 1u));
        int leader = __ffs(m) - 1;
        int basepos = 0;
        if (lane == leader) basepos = atomicAdd(&d_ncand, __popc(m));
        basepos = __shfl_sync(m, basepos, leader);
        int pos = basepos + nbefore;
        if (pos < CAND_CAP) {
            // key: descending score, then ascending index (matches jax top_k stability)
            d_ckey[pos] = ((ull)bits << 32) | (ull)(0xffffffffu - (unsigned)i);
            d_cidx[pos] = i;
        }
    }
}

// ---------------- rank-by-counting (exact permutation; keys all distinct) ----------------
// grid (CAND_CAP/512, CAND_CAP/2048); 2 candidates/thread (block covers 512),
// j-tile = 2048 keys (16 KB shared): each staged key serves 2 compares (halved LDS).
#define RT 2048
__global__ void k_rank() {
    int n = d_ncand; if (n > CAND_CAP) n = CAND_CAP;
    int c0 = blockIdx.x * 512;
    int j0 = blockIdx.y * RT;
    if (c0 >= n || j0 >= n) return;
    __shared__ ull sk[RT];
    int cA = c0 + threadIdx.x;
    int cB = c0 + 256 + threadIdx.x;
    ull keyA = (cA < n) ? d_ckey[cA] : ~0ull;
    ull keyB = (cB < n) ? d_ckey[cB] : ~0ull;
#pragma unroll
    for (int q = 0; q < RT / 256; q++) {
        int j = j0 + q * 256 + threadIdx.x;
        sk[q * 256 + threadIdx.x] = (j < n) ? d_ckey[j] : 0ull;
    }
    __syncthreads();
    int lim = n - j0; if (lim > RT) lim = RT;
    int a0 = 0, a1 = 0, b0 = 0, b1 = 0;       // split counters break add chains
    int j = 0;
    for (; j + 8 <= lim; j += 8) {
#pragma unroll
        for (int q = 0; q < 4; q++) {
            ull k0 = sk[j + q * 2 + 0];
            ull k1 = sk[j + q * 2 + 1];
            a0 += (k0 > keyA) ? 1 : 0;
            a1 += (k1 > keyA) ? 1 : 0;
            b0 += (k0 > keyB) ? 1 : 0;
            b1 += (k1 > keyB) ? 1 : 0;
        }
    }
    for (; j < lim; j++) {
        ull k0 = sk[j];
        a0 += (k0 > keyA) ? 1 : 0;
        b0 += (k0 > keyB) ? 1 : 0;
    }
    int ra = a0 + a1, rb = b0 + b1;
    if (cA < n && ra) atomicAdd(&d_rank[cA], ra);
    if (cB < n && rb) atomicAdd(&d_rank[cB], rb);
}

__global__ void k_gather() {
    int n = d_ncand; if (n > CAND_CAP) n = CAND_CAP;
    int c = blockIdx.x * blockDim.x + threadIdx.x;
    if (c >= n) return;
    int r = d_rank[c];
    if (r < KSEL) {
        int i = d_cidx[c];
        d_tbox[r] = d_boxes[i];
        d_tscore[r] = d_scores[i];
        d_tclass[r] = d_classes[i];
    }
}

// ---------------- IoU with hoisted areas (identical rounding to reference) ----------
__device__ __forceinline__ bool iou_gt2(const float4 a, float areaa,
                                        const float4 b, float areab) {
    float ty = fmaxf(a.x, b.x), tx = fmaxf(a.y, b.y);
    float by = fminf(a.z, b.z), bx = fminf(a.w, b.w);
    float ih = fmaxf(__fsub_rn(by, ty), 0.0f);
    float iw = fmaxf(__fsub_rn(bx, tx), 0.0f);
    float inter = __fmul_rn(ih, iw);
    float uni = __fsub_rn(__fadd_rn(areaa, areab), inter);
    return __fdiv_rn(inter, __fadd_rn(uni, 1e-9f)) > IOU_T;   // exact div: matches XLA bitwise
}

__device__ __forceinline__ float box_area(const float4 b) {
    return __fmul_rn(__fsub_rn(b.z, b.x), __fsub_rn(b.w, b.y));
}

// ---------------- chip-wide suppression-bit matrix build (antithetic pairing) ------
// 128 blocks x 512 threads (16 warps => 4 warps/SMSP for issue-latency hiding).
// Block b owns row-groups b AND 255-b => per-block word-step count ~constant (~128.5)
// despite the triangular skip; single balanced wave on 148 SMs.
// Each warp handles 2 rows of group A + 2 rows of group B; per jw step each lane's
// b0/b1 areas are hoisted once and reused across all 4 rows.
#define JT 2048          // j-tile boxes staged in shared
#define JTW (JT / 64)    // 32 words per tile
#define MT 512           // k_mask threads

__global__ void k_mask() {
    __shared__ float4 stile[JT];
    int warp = threadIdx.x >> 5, lane = threadIdx.x & 31;
    int baseA = blockIdx.x * 32 + warp * 2;              // group A (early rows), 2 rows/warp
    int baseB = (255 - blockIdx.x) * 32 + warp * 2;      // group B (late rows)
    int rwA = baseA >> 6, rwB = baseB >> 6;              // rwA < rwB (blockIdx < 128)
    float4 rbA[2], rbB[2]; float raA[2], raB[2];
#pragma unroll
    for (int r = 0; r < 2; r++) {
        rbA[r] = d_tbox[baseA + r];  raA[r] = box_area(rbA[r]);
        rbB[r] = d_tbox[baseB + r];  raB[r] = box_area(rbB[r]);
    }
    for (int t = 0; t < KSEL / JT; t++) {
        __syncthreads();
        for (int q = threadIdx.x; q < JT; q += MT)
            stile[q] = d_tbox[t * JT + q];
        __syncthreads();
        for (int wl = 0; wl < JTW; wl++) {
            int jw = t * JTW + wl;
            if (jw < rwA) continue;              // below both groups' triangles
            float4 b0 = stile[wl * 64 + lane];
            float4 b1 = stile[wl * 64 + 32 + lane];
            float ab0 = box_area(b0), ab1 = box_area(b1);   // hoisted: reused by up to 4 rows
            // --- group A (always active here) ---
            {
                ull myword = 0ull;               // lane r keeps row r's word
#pragma unroll
                for (int r = 0; r < 2; r++) {
                    unsigned m0 = __ballot_sync(0xffffffffu, iou_gt2(rbA[r], raA[r], b0, ab0));
                    unsigned m1 = __ballot_sync(0xffffffffu, iou_gt2(rbA[r], raA[r], b1, ab1));
                    if (lane == r) myword = ((ull)m1 << 32) | (ull)m0;
                }
                if (lane < 2) {                  // 2 parallel stores (one per row)
                    int i = baseA + lane;
                    if (jw == rwA)
                        d_diag[i] = myword & ~((2ull << (i & 63)) - 1ull);  // bits j > i
                    d_mask[(size_t)i * KW + jw] = myword;
                }
            }
            // --- group B (active for jw >= rwB; warp-uniform branch) ---
            if (jw >= rwB) {
                ull myword = 0ull;
#pragma unroll
                for (int r = 0; r < 2; r++) {
                    unsigned m0 = __ballot_sync(0xffffffffu, iou_gt2(rbB[r], raB[r], b0, ab0));
                    unsigned m1 = __ballot_sync(0xffffffffu, iou_gt2(rbB[r], raB[r], b1, ab1));
                    if (lane == r) myword = ((ull)m1 << 32) | (ull)m0;
                }
                if (lane < 2) {
                    int i = baseB + lane;
                    if (jw == rwB)
                        d_diag[i] = myword & ~((2ull << (i & 63)) - 1ull);
                    d_mask[(size_t)i * KW + jw] = myword;
                }
            }
        }
    }
}

// ---------------- serial greedy resolution on precomputed mask + emit ----------------
// Invariant: srem[w] is written only by forward suppression from chunks < w (exclusive
// owner thread, barrier-separated) and read only at chunk w. The chunk's final removed
// word (incl. within-chunk diag bits) lives in sfin[w], written only by tid 0.
#define RES_SMEM ((KSEL + KW + KW + KW + KW + 8) * 8)

__global__ void k_resolve(float* __restrict__ out) {
    extern __shared__ unsigned char sm[];
    ull* sdiag = (ull*)sm;             // 8192 words (64 KB)
    ull* srem = sdiag + KSEL;          // 128: forward-suppression accumulator
    ull* sfin = srem + KW;             // 128: final removed word per chunk
    ull* sval = sfin + KW;             // 128: valid (score>0) bits
    int* sbase = (int*)(sval + KW);    // 128 ints: output prefix bases
    ull* sacc = (ull*)(sbase + KW);    // broadcast accepted set
    int tid = threadIdx.x;             // 128 threads
    int lane = tid & 31;
    srem[tid] = 0ull; sval[tid] = 0ull;
    __syncthreads();

    // valid bits (score > 0), warp-ballot, coalesced
    for (int it = 0; it < KSEL / 128; it++) {
        int i = it * 128 + tid;
        unsigned m = __ballot_sync(0xffffffffu, d_tscore[i] > 0.0f);
        if (lane == 0) {
            int w = i >> 6, half = (i >> 5) & 1;
            atomicOr(&sval[w], ((ull)m) << (half * 32));
        }
    }
    // stage all diagonal words (contiguous, coalesced)
    for (int i = tid; i < KSEL; i += 128) sdiag[i] = d_diag[i];
    __syncthreads();

    for (int b = 0; b < KW; b++) {
        // srem[b] is final here (all writers ran in earlier iterations, barrier-separated)
        ull rem_b = srem[b];
        ull cand = sval[b] & ~rem_b;
        int w = b + 1 + tid;                     // exclusive owner thread per future word
        const ull* rowp = d_mask + (size_t)(b * 64) * KW + w;
        // Exact prefetch: greedy's first THREE accepted are determined at chunk entry:
        //   l0 = ffs(cand)
        //   l1 = ffs(cand & ~diag[l0] & bits>l0)
        //   l2 = ffs(cand & ~diag[l0] & ~diag[l1] & bits>l1)
        int l0 = -1, l1 = -1, l2 = -1;
        ull pre0 = 0ull, pre1 = 0ull, pre2 = 0ull;
        if (cand && w < KW) {
            l0 = __ffsll(cand) - 1;
            pre0 = rowp[(size_t)l0 * KW];        // overlaps tid0's serial walk below
            ull rest = cand & ~sdiag[b * 64 + l0] & ~((2ull << l0) - 1ull);
            if (rest) {
                l1 = __ffsll(rest) - 1;
                pre1 = rowp[(size_t)l1 * KW];
                ull rest2 = rest & ~sdiag[b * 64 + l1] & ~((2ull << l1) - 1ull);
                if (rest2) {
                    l2 = __ffsll(rest2) - 1;
                    pre2 = rowp[(size_t)l2 * KW];
                }
            }
        }
        if (tid == 0) {
            ull cur = rem_b, remaining = cand, acc = 0ull;
            while (remaining) {                  // steps == #accepted in chunk
                int l = __ffsll(remaining) - 1;
                acc |= (1ull << l);
                cur |= sdiag[b * 64 + l];
                remaining &= ~(cur | (1ull << l));
            }
            sfin[b] = cur;
            sacc[0] = acc;
        }
        __syncthreads();
        ull acc = sacc[0];
        if (acc && w < KW) {
            ull setbits = 0ull;
            ull a2 = acc;
            if (l0 >= 0) {                       // 1st candidate: always accepted
                setbits |= pre0;
                a2 &= ~(1ull << l0);
            }
            if (l1 >= 0 && (a2 & (1ull << l1))) {   // 2nd accepted (exact by construction)
                setbits |= pre1;
                a2 &= ~(1ull << l1);
            }
            if (l2 >= 0 && (a2 & (1ull << l2))) {   // 3rd accepted (exact by construction)
                setbits |= pre2;
                a2 &= ~(1ull << l2);
            }
            while (a2) {
                int l = __ffsll(a2) - 1; a2 &= a2 - 1ull;
                setbits |= rowp[(size_t)l * KW];  // coalesced across tid for fixed l
            }
            if (setbits) srem[w] |= setbits;      // exclusive owner: no atomic
        }
        __syncthreads();
    }

    // ---- emit top-300 (keep = valid & ~final_removed), rank order preserved ----
    ull keep = sval[tid] & ~sfin[tid];
    for (int i = tid; i < 1800; i += 128) out[i] = 0.0f;
    __syncthreads();
    if (tid == 0) {
        int run = 0;
        for (int w2 = 0; w2 < KW; w2++) {
            sbase[w2] = run;
            run += __popcll(sval[w2] & ~sfin[w2]);
        }
    }
    __syncthreads();
    {
        ull kw = keep;
        int r = sbase[tid];
        while (kw) {
            int l = __ffsll(kw) - 1; kw &= kw - 1ull;
            if (r < MAXD) {
                int i = tid * 64 + l;
                float4 bx = d_tbox[i];
                out[4 * r + 0] = bx.x; out[4 * r + 1] = bx.y;
                out[4 * r + 2] = bx.z; out[4 * r + 3] = bx.w;
                out[1200 + r] = d_tclass[i];
                out[1500 + r] = d_tscore[i];
            }
            r++;
        }
    }
}

// ---------------- launch ----------------
extern "C" void kernel_launch(void* const* d_in, const int* in_sizes, int n_in,
                              void* d_out, int out_size) {
    const float* preds = (const float*)d_in[0];
    float* out = (float*)d_out;
    cudaFuncSetAttribute(k_resolve, cudaFuncAttributeMaxDynamicSharedMemorySize, RES_SMEM);

    k_init<<<(65536 + 255) / 256, 256>>>();
    k_score<<<(NA + 127) / 128, 128>>>(preds);
    k_cutoff<<<1, 1024>>>();
    k_compact<<<(NA + 255) / 256, 256>>>();
    k_rank<<<dim3(CAND_CAP / 512, CAND_CAP / RT, 1), 256>>>();
    k_gather<<<64, 256>>>();
    k_mask<<<KSEL / 64, MT>>>();
    k_resolve<<<1, 128, RES_SMEM>>>(out);
}

// round 14
// speedup vs baseline: 1.1047x; 1.1047x over previous
#include <cuda_runtime.h>

#define NA 102000
#define DIMS 85
#define NCLS 80
#define KSEL 8192
#define KW 128           // 8192/64 words
#define MAXD 300
#define CAND_CAP 16384
#define CONF_T 0.25f
#define IOU_T 0.45f

typedef unsigned long long ull;

// ---------------- scratch (__device__ globals; no allocation) ----------------
__device__ float d_scores[NA];
__device__ float d_classes[NA];
__device__ float4 d_boxes[NA];          // yxyx
__device__ unsigned int d_hist[65536];  // zero-init at load; self-cleaned by k_cutoff
__device__ int d_binB;
__device__ int d_ncand;                 // self-cleaned by k_cutoff
__device__ ull d_ckey[CAND_CAP];
__device__ int d_cidx[CAND_CAP];
__device__ int d_rank[CAND_CAP];        // self-cleaned by k_cutoff
__device__ float4 d_tbox[KSEL];
__device__ float d_tscore[KSEL];
__device__ float d_tclass[KSEL];
__device__ ull d_mask[(size_t)KSEL * KW];   // 8 MB suppression-bit matrix (upper triangle)
__device__ ull d_diag[KSEL];                // each row's own-chunk word (bits j>i only)

// ---------------- scoring + histogram ----------------
__global__ void k_score(const float* __restrict__ preds) {
    __shared__ float sp[128 * DIMS];
    int base = blockIdx.x * 128;
    int nanch = NA - base; if (nanch > 128) nanch = 128;
    int total = nanch * DIMS;                     // divisible by 4 (nanch % 4 == 0 incl. tail 112)
    const float4* src4 = (const float4*)(preds + (size_t)base * DIMS);
    float4* sp4 = (float4*)sp;
    int total4 = total >> 2;
    for (int i = threadIdx.x; i < total4; i += 128) sp4[i] = src4[i];
    __syncthreads();

    int a = threadIdx.x;
    unsigned amask = __ballot_sync(0xffffffffu, a < nanch);
    if (a >= nanch) return;

    const float* p = sp + a * DIMS;
    float obj = p[4];
    float best = -1.0f; int bc = 0;
#pragma unroll
    for (int c = 0; c < NCLS; c++) {
        float v = __fmul_rn(p[5 + c], obj);   // per-class product, first-max argmax (matches jnp.argmax)
        if (v > best) { best = v; bc = c; }
    }
    float score = (obj > CONF_T) ? best : 0.0f;
    int gi = base + a;
    d_scores[gi] = score;
    d_classes[gi] = (float)bc;
    float x = p[0], y = p[1], w = p[2], h = p[3];
    float hw = __fmul_rn(w, 0.5f), hh = __fmul_rn(h, 0.5f);   // exact (x0.5)
    d_boxes[gi] = make_float4(__fsub_rn(y, hh), __fsub_rn(x, hw),
                              __fadd_rn(y, hh), __fadd_rn(x, hw));

    int bin = (int)(__float_as_uint(score) >> 16);   // score >= 0 -> monotone bits
    unsigned grp = __match_any_sync(amask, bin);
    int leader = __ffs(grp) - 1;
    if ((int)(threadIdx.x & 31) == leader)
        atomicAdd(&d_hist[bin], (unsigned)__popc(grp));
}

// ---------------- find cutoff bin + self-clean scratch for next replay ----------------
__global__ void k_cutoff() {
    __shared__ unsigned int ssum[1024];
    __shared__ unsigned int ssuf[1024];
    int t = threadIdx.x;
    int b0 = t * 64;
    unsigned s = 0;
    const uint4* h4 = (const uint4*)(d_hist + b0);   // 64 bins = 16 uint4 (16B-aligned)
#pragma unroll
    for (int k = 0; k < 16; k++) {
        uint4 v = h4[k];
        s += v.x + v.y + v.z + v.w;
    }
    ssum[t] = s; ssuf[t] = s;
    __syncthreads();
    for (int off = 1; off < 1024; off <<= 1) {   // inclusive suffix scan
        unsigned add = (t + off < 1024) ? ssuf[t + off] : 0u;
        __syncthreads();
        ssuf[t] += add;
        __syncthreads();
    }
    unsigned excl = (t < 1023) ? ssuf[t + 1] : 0u;
    if (excl < KSEL && excl + ssum[t] >= KSEL) {
        unsigned acc = excl;
        int bin = b0;
        for (int k = 63; k >= 0; k--) {
            acc += d_hist[b0 + k];
            if (acc >= KSEL) { bin = b0 + k; break; }
        }
        d_binB = bin;
    }
    // self-clean for next graph replay (per-thread ordering: own reads precede own zeroes)
    {
        uint4 z = make_uint4(0u, 0u, 0u, 0u);
        uint4* h4w = (uint4*)(d_hist + b0);
#pragma unroll
        for (int k = 0; k < 16; k++) h4w[k] = z;
        d_rank[t] = 0;               // 1024 threads x 16 = 16384
        d_rank[t + 1024] = 0;  d_rank[t + 2048] = 0;  d_rank[t + 3072] = 0;
        d_rank[t + 4096] = 0;  d_rank[t + 5120] = 0;  d_rank[t + 6144] = 0;
        d_rank[t + 7168] = 0;  d_rank[t + 8192] = 0;  d_rank[t + 9216] = 0;
        d_rank[t + 10240] = 0; d_rank[t + 11264] = 0; d_rank[t + 12288] = 0;
        d_rank[t + 13312] = 0; d_rank[t + 14336] = 0; d_rank[t + 15360] = 0;
        if (t == 0) d_ncand = 0;     // before k_compact in stream order
    }
}

// ---------------- compact candidates (key16 >= cutoff bin, nonzero) ----------------
__global__ void k_compact() {
    int i = blockIdx.x * blockDim.x + threadIdx.x;
    bool q = false;
    unsigned bits = 0;
    if (i < NA) {
        bits = __float_as_uint(d_scores[i]);
        q = (bits != 0u) && ((int)(bits >> 16) >= d_binB);
    }
    unsigned m = __ballot_sync(0xffffffffu, q);
    if (q) {
        int lane = threadIdx.x & 31;
        int nbefore = __popc(m & ((1u << lane) - 1u));
        int leader = __ffs(m) - 1;
        int basepos = 0;
        if (lane == leader) basepos = atomicAdd(&d_ncand, __popc(m));
        basepos = __shfl_sync(m, basepos, leader);
        int pos = basepos + nbefore;
        if (pos < CAND_CAP) {
            // key: descending score, then ascending index (matches jax top_k stability)
            d_ckey[pos] = ((ull)bits << 32) | (ull)(0xffffffffu - (unsigned)i);
            d_cidx[pos] = i;
        }
    }
}

// ---------------- rank-by-counting (exact permutation; keys all distinct) ----------------
// grid (CAND_CAP/512, CAND_CAP/2048); 2 candidates/thread (block covers 512),
// j-tile = 2048 keys (16 KB shared): each staged key serves 2 compares (halved LDS).
#define RT 2048
__global__ void k_rank() {
    int n = d_ncand; if (n > CAND_CAP) n = CAND_CAP;
    int c0 = blockIdx.x * 512;
    int j0 = blockIdx.y * RT;
    if (c0 >= n || j0 >= n) return;
    __shared__ ull sk[RT];
    int cA = c0 + threadIdx.x;
    int cB = c0 + 256 + threadIdx.x;
    ull keyA = (cA < n) ? d_ckey[cA] : ~0ull;
    ull keyB = (cB < n) ? d_ckey[cB] : ~0ull;
#pragma unroll
    for (int q = 0; q < RT / 256; q++) {
        int j = j0 + q * 256 + threadIdx.x;
        sk[q * 256 + threadIdx.x] = (j < n) ? d_ckey[j] : 0ull;
    }
    __syncthreads();
    int lim = n - j0; if (lim > RT) lim = RT;
    int a0 = 0, a1 = 0, b0 = 0, b1 = 0;       // split counters break add chains
    int j = 0;
    for (; j + 8 <= lim; j += 8) {
#pragma unroll
        for (int q = 0; q < 4; q++) {
            ull k0 = sk[j + q * 2 + 0];
            ull k1 = sk[j + q * 2 + 1];
            a0 += (k0 > keyA) ? 1 : 0;
            a1 += (k1 > keyA) ? 1 : 0;
            b0 += (k0 > keyB) ? 1 : 0;
            b1 += (k1 > keyB) ? 1 : 0;
        }
    }
    for (; j < lim; j++) {
        ull k0 = sk[j];
        a0 += (k0 > keyA) ? 1 : 0;
        b0 += (k0 > keyB) ? 1 : 0;
    }
    int ra = a0 + a1, rb = b0 + b1;
    if (cA < n && ra) atomicAdd(&d_rank[cA], ra);
    if (cB < n && rb) atomicAdd(&d_rank[cB], rb);
}

__global__ void k_gather() {
    int n = d_ncand; if (n > CAND_CAP) n = CAND_CAP;
    int c = blockIdx.x * blockDim.x + threadIdx.x;
    if (c >= n) return;
    int r = d_rank[c];
    if (r < KSEL) {
        int i = d_cidx[c];
        d_tbox[r] = d_boxes[i];
        d_tscore[r] = d_scores[i];
        d_tclass[r] = d_classes[i];
    }
}

// ---------------- IoU decision: interval compare + exact-div fallback ----------------
// RN(inter/d) > T decided without division except within a +-6e-7 rel band around the
// threshold (expected ~4 fallbacks in 33.5M pairs). Fallback path is the bit-exact
// __fdiv_rn compare, so the decision is ALWAYS identical to the reference's div.rn.
__device__ __forceinline__ bool iou_gt2(const float4 a, float areaa,
                                        const float4 b, float areab) {
    float ty = fmaxf(a.x, b.x), tx = fmaxf(a.y, b.y);
    float by = fminf(a.z, b.z), bx = fminf(a.w, b.w);
    float ih = fmaxf(__fsub_rn(by, ty), 0.0f);
    float iw = fmaxf(__fsub_rn(bx, tx), 0.0f);
    float inter = __fmul_rn(ih, iw);
    float uni = __fsub_rn(__fadd_rn(areaa, areab), inter);
    float d = __fadd_rn(uni, 1e-9f);             // d > 0 always (areas > 0)
    float c = __fmul_rn(IOU_T, d);
    float marg = __fmul_rn(c, 6e-7f);
    if (inter > __fadd_rn(c, marg)) return true;     // certified: RN(inter/d) > T
    if (inter < __fsub_rn(c, marg)) return false;    // certified: RN(inter/d) <= T
    return __fdiv_rn(inter, d) > IOU_T;              // rare exact path (bit-identical)
}

__device__ __forceinline__ float box_area(const float4 b) {
    return __fmul_rn(__fsub_rn(b.z, b.x), __fsub_rn(b.w, b.y));
}

// ---------------- chip-wide suppression-bit matrix build (antithetic pairing) ------
// 128 blocks x 512 threads (16 warps => 4 warps/SMSP for issue-latency hiding).
// Block b owns row-groups b AND 255-b => per-block word-step count ~constant (~128.5)
// despite the triangular skip; single balanced wave on 148 SMs.
#define JT 2048          // j-tile boxes staged in shared
#define JTW (JT / 64)    // 32 words per tile
#define MT 512           // k_mask threads

__global__ void k_mask() {
    __shared__ float4 stile[JT];
    int warp = threadIdx.x >> 5, lane = threadIdx.x & 31;
    int baseA = blockIdx.x * 32 + warp * 2;              // group A (early rows), 2 rows/warp
    int baseB = (255 - blockIdx.x) * 32 + warp * 2;      // group B (late rows)
    int rwA = baseA >> 6, rwB = baseB >> 6;              // rwA < rwB (blockIdx < 128)
    float4 rbA[2], rbB[2]; float raA[2], raB[2];
#pragma unroll
    for (int r = 0; r < 2; r++) {
        rbA[r] = d_tbox[baseA + r];  raA[r] = box_area(rbA[r]);
        rbB[r] = d_tbox[baseB + r];  raB[r] = box_area(rbB[r]);
    }
    for (int t = 0; t < KSEL / JT; t++) {
        __syncthreads();
        for (int q = threadIdx.x; q < JT; q += MT)
            stile[q] = d_tbox[t * JT + q];
        __syncthreads();
        for (int wl = 0; wl < JTW; wl++) {
            int jw = t * JTW + wl;
            if (jw < rwA) continue;              // below both groups' triangles
            float4 b0 = stile[wl * 64 + lane];
            float4 b1 = stile[wl * 64 + 32 + lane];
            float ab0 = box_area(b0), ab1 = box_area(b1);   // hoisted: reused by up to 4 rows
            // --- group A (always active here) ---
            {
                ull myword = 0ull;               // lane r keeps row r's word
#pragma unroll
                for (int r = 0; r < 2; r++) {
                    unsigned m0 = __ballot_sync(0xffffffffu, iou_gt2(rbA[r], raA[r], b0, ab0));
                    unsigned m1 = __ballot_sync(0xffffffffu, iou_gt2(rbA[r], raA[r], b1, ab1));
                    if (lane == r) myword = ((ull)m1 << 32) | (ull)m0;
                }
                if (lane < 2) {                  // 2 parallel stores (one per row)
                    int i = baseA + lane;
                    if (jw == rwA)
                        d_diag[i] = myword & ~((2ull << (i & 63)) - 1ull);  // bits j > i
                    d_mask[(size_t)i * KW + jw] = myword;
                }
            }
            // --- group B (active for jw >= rwB; warp-uniform branch) ---
            if (jw >= rwB) {
                ull myword = 0ull;
#pragma unroll
                for (int r = 0; r < 2; r++) {
                    unsigned m0 = __ballot_sync(0xffffffffu, iou_gt2(rbB[r], raB[r], b0, ab0));
                    unsigned m1 = __ballot_sync(0xffffffffu, iou_gt2(rbB[r], raB[r], b1, ab1));
                    if (lane == r) myword = ((ull)m1 << 32) | (ull)m0;
                }
                if (lane < 2) {
                    int i = baseB + lane;
                    if (jw == rwB)
                        d_diag[i] = myword & ~((2ull << (i & 63)) - 1ull);
                    d_mask[(size_t)i * KW + jw] = myword;
                }
            }
        }
    }
}

// ---------------- serial greedy resolution on precomputed mask + emit ----------------
// Invariant: srem[w] is written only by forward suppression from chunks < w (exclusive
// owner thread, barrier-separated) and read only at chunk w. The chunk's final removed
// word (incl. within-chunk diag bits) lives in sfin[w], written only by tid 0.
#define RES_SMEM ((KSEL + KW + KW + KW + KW + 8) * 8)

__global__ void k_resolve(float* __restrict__ out) {
    extern __shared__ unsigned char sm[];
    ull* sdiag = (ull*)sm;             // 8192 words (64 KB)
    ull* srem = sdiag + KSEL;          // 128: forward-suppression accumulator
    ull* sfin = srem + KW;             // 128: final removed word per chunk
    ull* sval = sfin + KW;             // 128: valid (score>0) bits
    int* sbase = (int*)(sval + KW);    // 128 ints: output prefix bases
    ull* sacc = (ull*)(sbase + KW);    // broadcast accepted set
    int tid = threadIdx.x;             // 128 threads
    int lane = tid & 31;
    srem[tid] = 0ull; sval[tid] = 0ull;
    __syncthreads();

    // valid bits (score > 0), warp-ballot, coalesced
    for (int it = 0; it < KSEL / 128; it++) {
        int i = it * 128 + tid;
        unsigned m = __ballot_sync(0xffffffffu, d_tscore[i] > 0.0f);
        if (lane == 0) {
            int w = i >> 6, half = (i >> 5) & 1;
            atomicOr(&sval[w], ((ull)m) << (half * 32));
        }
    }
    // stage all diagonal words (contiguous, coalesced)
    for (int i = tid; i < KSEL; i += 128) sdiag[i] = d_diag[i];
    __syncthreads();

    for (int b = 0; b < KW; b++) {
        // srem[b] is final here (all writers ran in earlier iterations, barrier-separated)
        ull rem_b = srem[b];
        ull cand = sval[b] & ~rem_b;
        int w = b + 1 + tid;                     // exclusive owner thread per future word
        const ull* rowp = d_mask + (size_t)(b * 64) * KW + w;
        // Exact prefetch: greedy's first FOUR accepted are determined at chunk entry:
        //   l0 = ffs(cand); l_{k+1} = ffs(rest_k & ~diag[l_k] & bits>l_k)
        int l0 = -1, l1 = -1, l2 = -1, l3 = -1;
        ull pre0 = 0ull, pre1 = 0ull, pre2 = 0ull, pre3 = 0ull;
        if (cand && w < KW) {
            l0 = __ffsll(cand) - 1;
            pre0 = rowp[(size_t)l0 * KW];        // overlaps tid0's serial walk below
            ull rest = cand & ~sdiag[b * 64 + l0] & ~((2ull << l0) - 1ull);
            if (rest) {
                l1 = __ffsll(rest) - 1;
                pre1 = rowp[(size_t)l1 * KW];
                ull rest2 = rest & ~sdiag[b * 64 + l1] & ~((2ull << l1) - 1ull);
                if (rest2) {
                    l2 = __ffsll(rest2) - 1;
                    pre2 = rowp[(size_t)l2 * KW];
                    ull rest3 = rest2 & ~sdiag[b * 64 + l2] & ~((2ull << l2) - 1ull);
                    if (rest3) {
                        l3 = __ffsll(rest3) - 1;
                        pre3 = rowp[(size_t)l3 * KW];
                    }
                }
            }
        }
        if (tid == 0) {
            ull cur = rem_b, remaining = cand, acc = 0ull;
            while (remaining) {                  // steps == #accepted in chunk
                int l = __ffsll(remaining) - 1;
                acc |= (1ull << l);
                cur |= sdiag[b * 64 + l];
                remaining &= ~(cur | (1ull << l));
            }
            sfin[b] = cur;
            sacc[0] = acc;
        }
        __syncthreads();
        ull acc = sacc[0];
        if (acc && w < KW) {
            ull setbits = 0ull;
            ull a2 = acc;
            if (l0 >= 0) {                       // 1st candidate: always accepted
                setbits |= pre0;
                a2 &= ~(1ull << l0);
            }
            if (l1 >= 0 && (a2 & (1ull << l1))) {   // 2nd accepted (exact by construction)
                setbits |= pre1;
                a2 &= ~(1ull << l1);
            }
            if (l2 >= 0 && (a2 & (1ull << l2))) {   // 3rd accepted
                setbits |= pre2;
                a2 &= ~(1ull << l2);
            }
            if (l3 >= 0 && (a2 & (1ull << l3))) {   // 4th accepted
                setbits |= pre3;
                a2 &= ~(1ull << l3);
            }
            while (a2) {
                int l = __ffsll(a2) - 1; a2 &= a2 - 1ull;
                setbits |= rowp[(size_t)l * KW];  // coalesced across tid for fixed l
            }
            if (setbits) srem[w] |= setbits;      // exclusive owner: no atomic
        }
        __syncthreads();
    }

    // ---- emit top-300 (keep = valid & ~final_removed), rank order preserved ----
    ull keep = sval[tid] & ~sfin[tid];
    for (int i = tid; i < 1800; i += 128) out[i] = 0.0f;
    __syncthreads();
    if (tid == 0) {
        int run = 0;
        for (int w2 = 0; w2 < KW; w2++) {
            sbase[w2] = run;
            run += __popcll(sval[w2] & ~sfin[w2]);
        }
    }
    __syncthreads();
    {
        ull kw = keep;
        int r = sbase[tid];
        while (kw) {
            int l = __ffsll(kw) - 1; kw &= kw - 1ull;
            if (r < MAXD) {
                int i = tid * 64 + l;
                float4 bx = d_tbox[i];
                out[4 * r + 0] = bx.x; out[4 * r + 1] = bx.y;
                out[4 * r + 2] = bx.z; out[4 * r + 3] = bx.w;
                out[1200 + r] = d_tclass[i];
                out[1500 + r] = d_tscore[i];
            }
            r++;
        }
    }
}

// ---------------- launch ----------------
extern "C" void kernel_launch(void* const* d_in, const int* in_sizes, int n_in,
                              void* d_out, int out_size) {
    const float* preds = (const float*)d_in[0];
    float* out = (float*)d_out;
    cudaFuncSetAttribute(k_resolve, cudaFuncAttributeMaxDynamicSharedMemorySize, RES_SMEM);

    k_score<<<(NA + 127) / 128, 128>>>(preds);
    k_cutoff<<<1, 1024>>>();
    k_compact<<<(NA + 255) / 256, 256>>>();
    k_rank<<<dim3(CAND_CAP / 512, CAND_CAP / RT, 1), 256>>>();
    k_gather<<<64, 256>>>();
    k_mask<<<KSEL / 64, MT>>>();
    k_resolve<<<1, 128, RES_SMEM>>>(out);
}